// round 17
// baseline (speedup 1.0000x reference)
#include <cuda_runtime.h>
#include <cstdint>

// ============================================================================
// out[M,N] = (clip(round(x/inscale)) int8) @ weight[N,K]^T * alpha
// M=8192, K=4096, N=4096.  Legacy-tensor-pipe bound; R12 measured 1897us at
// tensor=94.4%, occ=24%.  R13-R16: persistent grid (296 CTAs, ~7 tiles each)
// with a continuous cp.async ring across tile boundaries (hides wave-
// transition pipeline drains + overlaps epilogues), fused convert+quant.
// ============================================================================

#define MM 8192
#define NN 4096
#define KDIM 4096
#define BM 128
#define BN 128
#define BK 128                 // int8 elems (=bytes) per K-chunk
#define STAGES 3
#define THREADS 256
#define KITERS (KDIM / BK)     // 32 k-chunks per tile
#define NTILES ((MM / BM) * (NN / BN))   // 2048
#define GRID_P 296             // 148 SMs x 2 CTAs resident

#define ASTAGE (BM * BK)                   // 16384 B
#define BSTAGE (BN * BK)                   // 16384 B
#define STAGE_BYTES (ASTAGE + BSTAGE)      // 32768 B
#define SMEM_TOTAL (STAGES * STAGE_BYTES)  // 98304 B -> 2 CTAs/SM

// device scratch (allocation-free)
__device__ int8_t g_q[(size_t)MM * (size_t)KDIM];   // quantized activations
__device__ int8_t g_w[(size_t)NN * (size_t)KDIM];   // normalized int8 weight
__device__ int    g_w_mode;                          // 0=int8, 1=int32, 2=f32

// ---------------------------------------------------------------------------
__device__ __forceinline__ uint32_t smem_u32(const void* p) {
    uint32_t a;
    asm("{ .reg .u64 t; cvta.to.shared.u64 t, %1; cvt.u32.u64 %0, t; }"
        : "=r"(a) : "l"(p));
    return a;
}

__device__ __forceinline__ void cp16(uint32_t dst, const void* src) {
    asm volatile("cp.async.cg.shared.global [%0], [%1], 16;"
                 :: "r"(dst), "l"(src));
}

#define CP_COMMIT() asm volatile("cp.async.commit_group;" ::: "memory")
#define CP_WAIT1()  asm volatile("cp.async.wait_group 1;" ::: "memory")

__device__ __forceinline__ uint32_t lds32(uint32_t addr) {
    uint32_t v;
    asm volatile("ld.shared.b32 %0, [%1];" : "=r"(v) : "r"(addr));
    return v;
}

__device__ __forceinline__ void mma_s8(int* c, const uint32_t* a, const uint32_t* b) {
    asm volatile(
        "mma.sync.aligned.m16n8k32.row.col.s32.s8.s8.s32 "
        "{%0,%1,%2,%3}, {%4,%5,%6,%7}, {%8,%9}, {%0,%1,%2,%3};"
        : "+r"(c[0]), "+r"(c[1]), "+r"(c[2]), "+r"(c[3])
        : "r"(a[0]), "r"(a[1]), "r"(a[2]), "r"(a[3]), "r"(b[0]), "r"(b[1]));
}

// XOR swizzle for 128-byte rows: chunk(16B) index ^= (row & 7).
// Same bijection for cp.async stores and fragment loads; conflict-free.
__device__ __forceinline__ uint32_t swz(int row, int chunk16) {
    return (uint32_t)(row * 128) + (uint32_t)((chunk16 ^ (row & 7)) * 16);
}

// ---------------------------------------------------------------------------
// Kernel 0a: detect weight storage format from the first 8192 32-bit words.
//   int32 storage: every word in [-128,127]        (raw int8: p ~ 2^-24/word)
//   float32 storage: every word is an integral-valued float, |v| <= 127
// ---------------------------------------------------------------------------
__global__ void detect_kernel(const int* __restrict__ w) {
    __shared__ int cnt_i32, cnt_f32;
    if (threadIdx.x == 0) { cnt_i32 = 0; cnt_f32 = 0; }
    __syncthreads();
    int li = 0, lf = 0;
    for (int j = 0; j < 32; j++) {
        int v = w[threadIdx.x * 32 + j];
        if (v >= -128 && v <= 127) li++;
        float f = __int_as_float(v);
        if (f == rintf(f) && fabsf(f) <= 127.0f) lf++;
    }
    atomicAdd(&cnt_i32, li);
    atomicAdd(&cnt_f32, lf);
    __syncthreads();
    if (threadIdx.x == 0) {
        int mode = 0;
        if (cnt_i32 >= 4096) mode = 1;
        else if (cnt_f32 >= 4096) mode = 2;
        g_w_mode = mode;
    }
}

// ---------------------------------------------------------------------------
// Kernel 0b+1 fused: blocks [0, WBLK) normalize the weight into g_w;
// blocks [WBLK, WBLK+QBLK) quantize activations into g_q.  Independent
// streams overlap instead of serializing as two launches.
// ---------------------------------------------------------------------------
#define WBLK (((size_t)NN * KDIM / 4) / 256)     // 16384
#define QBLK (((size_t)MM * KDIM / 4) / 256)     // 32768

__global__ void __launch_bounds__(256)
pre_kernel(const void* __restrict__ w, const float* __restrict__ x,
           const float* __restrict__ inscale_p) {
    if (blockIdx.x < WBLK) {
        const size_t i = (size_t)blockIdx.x * 256 + threadIdx.x;  // char4 idx
        const int mode = g_w_mode;
        char4 c;
        if (mode == 1) {
            int4 v = reinterpret_cast<const int4*>(w)[i];
            c.x = (char)v.x; c.y = (char)v.y; c.z = (char)v.z; c.w = (char)v.w;
        } else if (mode == 2) {
            float4 v = reinterpret_cast<const float4*>(w)[i];
            c.x = (char)(int)v.x; c.y = (char)(int)v.y;
            c.z = (char)(int)v.z; c.w = (char)(int)v.w;
        } else {
            c = reinterpret_cast<const char4*>(w)[i];
        }
        reinterpret_cast<char4*>(g_w)[i] = c;
    } else {
        // __fdiv_rn: IEEE division even under fast-math -> rintf bit-matches
        // jnp.round(xf / inscale) (round-half-even on the exact quotient).
        const float s = *inscale_p;
        const size_t i = (size_t)(blockIdx.x - WBLK) * 256 + threadIdx.x;
        float4 v = reinterpret_cast<const float4*>(x)[i];
        char4 q;
        q.x = (char)(int)fminf(127.f, fmaxf(-128.f, rintf(__fdiv_rn(v.x, s))));
        q.y = (char)(int)fminf(127.f, fmaxf(-128.f, rintf(__fdiv_rn(v.y, s))));
        q.z = (char)(int)fminf(127.f, fmaxf(-128.f, rintf(__fdiv_rn(v.z, s))));
        q.w = (char)(int)fminf(127.f, fmaxf(-128.f, rintf(__fdiv_rn(v.w, s))));
        reinterpret_cast<char4*>(g_q)[i] = q;
    }
}

// ---------------------------------------------------------------------------
// Kernel 2: persistent int8 tensor-core GEMM + fused alpha-dequant epilogue.
// Each CTA sweeps tiles {bid, bid+296, ...}; the cp.async stage ring runs
// continuously across tile boundaries (loads lead compute by 2 iterations,
// including across the tile switch), so epilogues overlap the next tile's
// global loads and there is no per-tile pipeline refill.
// ---------------------------------------------------------------------------
__global__ void __launch_bounds__(THREADS, 2)
gemm_kernel(float* __restrict__ out, const float* __restrict__ alpha_p) {
    extern __shared__ char smem[];
    const uint32_t sbase = smem_u32(smem);
    const int tid = threadIdx.x;
    const int wid = tid >> 5;
    const int lid = tid & 31;

    const int warp_m = wid & 3;                 // 4 warps along M
    const int warp_n = wid >> 2;                // 2 warps along N

    // tiles for this CTA: pid = bid + tix*GRID_P < NTILES
    const int bid = blockIdx.x;
    const int my_tiles = (NTILES - 1 - bid) / GRID_P + 1;
    const int total_it = my_tiles * KITERS;

    // pid -> (m0, n0) with the L2 tile swizzle (16 M-tiles sweep all N-tiles)
    auto tile_coords = [&](int tix, int& m0, int& n0) {
        const int pid = bid + tix * GRID_P;
        const int grid_n = NN / BN;             // 32
        const int group = pid / (16 * grid_n);
        const int rem = pid % (16 * grid_n);
        m0 = (group * 16 + (rem & 15)) * BM;
        n0 = (rem >> 4) * BN;
    };

    // PTX-ISA m16n8k32.s8 fragment addresses (explicit scalar loads):
    //  A a0: row = warp_m*32 + mi*16 + lid/4, k-bytes 4*(lid%4) of chunk 2ks
    //    a1: row+8 same chunk; a2/a3: chunk 2ks+1
    //  B b0: n = warp_n*64 + ni*8 + lid/4, chunk 2ks;  b1: chunk 2ks+1
    const int frow = lid >> 2;            // 0..7
    const int fbyte = (lid & 3) * 4;      // 0,4,8,12

    int acc[2][8][4] = {};

    // load global iteration j (tile j/32, k-chunk j%32) into stage j%3
    auto load_iter = [&](int j) {
        const int tix = j >> 5;
        const int kk0 = (j & 31) * BK;
        const int stg = j % STAGES;
        int m0, n0;
        tile_coords(tix, m0, n0);
        const int8_t* aptr = g_q + (size_t)m0 * KDIM;
        const int8_t* bptr = g_w + (size_t)n0 * KDIM;
        const uint32_t abase = sbase + stg * STAGE_BYTES;
        const uint32_t bbase = abase + ASTAGE;
#pragma unroll
        for (int i = 0; i < 4; i++) {           // A: 128 rows x 8 chunks
            int idx = tid + i * THREADS;
            int row = idx >> 3, c = idx & 7;
            cp16(abase + swz(row, c), aptr + (size_t)row * KDIM + kk0 + c * 16);
        }
#pragma unroll
        for (int i = 0; i < 4; i++) {           // B: 128 rows x 8 chunks
            int idx = tid + i * THREADS;
            int row = idx >> 3, c = idx & 7;
            cp16(bbase + swz(row, c), bptr + (size_t)row * KDIM + kk0 + c * 16);
        }
    };

    auto compute_stage = [&](int stg) {
        const uint32_t abase = sbase + stg * STAGE_BYTES;
        const uint32_t bbase = abase + ASTAGE;
#pragma unroll
        for (int ks = 0; ks < 4; ks++) {
            const int c0 = ks * 2, c1 = ks * 2 + 1;
            uint32_t af[2][4];
#pragma unroll
            for (int mi = 0; mi < 2; mi++) {
                const int r = warp_m * 32 + mi * 16 + frow;
                af[mi][0] = lds32(abase + swz(r,     c0) + fbyte);
                af[mi][1] = lds32(abase + swz(r + 8, c0) + fbyte);
                af[mi][2] = lds32(abase + swz(r,     c1) + fbyte);
                af[mi][3] = lds32(abase + swz(r + 8, c1) + fbyte);
            }
            uint32_t bf[8][2];
#pragma unroll
            for (int ni = 0; ni < 8; ni++) {
                const int r = warp_n * 64 + ni * 8 + frow;
                bf[ni][0] = lds32(bbase + swz(r, c0) + fbyte);
                bf[ni][1] = lds32(bbase + swz(r, c1) + fbyte);
            }
#pragma unroll
            for (int mi = 0; mi < 2; mi++)
#pragma unroll
                for (int ni = 0; ni < 8; ni++)
                    mma_s8(acc[mi][ni], af[mi], bf[ni]);
        }
    };

    // prologue: 2 iterations in flight
    load_iter(0);
    CP_COMMIT();
    if (total_it > 1) load_iter(1);
    CP_COMMIT();

    const float alpha = *alpha_p;

    for (int j = 0; j < total_it; j++) {
        CP_WAIT1();          // iteration j's group complete (<=1 pending)
        __syncthreads();     // all warps done with the stage we refill next
        if (j + 2 < total_it) load_iter(j + 2);
        CP_COMMIT();         // (possibly empty group: keeps count aligned)
        compute_stage(j % STAGES);

        if ((j & 31) == 31) {
            // tile finished: epilogue (regs -> gmem), reset accumulators.
            // No sync needed: acc is register-local; next loop's sync
            // re-aligns warps before the stage buffer is reused.
            int m0, n0;
            tile_coords(j >> 5, m0, n0);
            const int r0 = m0 + warp_m * 32 + (lid >> 2);
            const int c0 = n0 + warp_n * 64 + (lid & 3) * 2;
#pragma unroll
            for (int mi = 0; mi < 2; mi++) {
#pragma unroll
                for (int ni = 0; ni < 8; ni++) {
                    const int row = r0 + mi * 16;
                    const int col = c0 + ni * 8;
                    float2 v0, v1;
                    v0.x = (float)acc[mi][ni][0] * alpha;
                    v0.y = (float)acc[mi][ni][1] * alpha;
                    v1.x = (float)acc[mi][ni][2] * alpha;
                    v1.y = (float)acc[mi][ni][3] * alpha;
                    *reinterpret_cast<float2*>(out + (size_t)row * NN + col) = v0;
                    *reinterpret_cast<float2*>(out + (size_t)(row + 8) * NN + col) = v1;
                    acc[mi][ni][0] = 0; acc[mi][ni][1] = 0;
                    acc[mi][ni][2] = 0; acc[mi][ni][3] = 0;
                }
            }
        }
    }
}

// ---------------------------------------------------------------------------
extern "C" void kernel_launch(void* const* d_in, const int* in_sizes, int n_in,
                              void* d_out, int out_size) {
    const float* x       = (const float*)d_in[0];
    const void*  w       = d_in[1];
    const float* alpha   = (const float*)d_in[2];
    const float* inscale = (const float*)d_in[3];
    float*       out     = (float*)d_out;
    (void)in_sizes; (void)n_in; (void)out_size;

    // 0) detect weight storage (int8 / int32 / float32)
    detect_kernel<<<1, 256>>>((const int*)w);

    // 1) fused: normalize weight -> g_w  ||  quantize activations -> g_q
    pre_kernel<<<(unsigned)(WBLK + QBLK), 256>>>(w, x, inscale);

    // 2) persistent int8 tensor-core GEMM + dequant
    cudaFuncSetAttribute(gemm_kernel, cudaFuncAttributeMaxDynamicSharedMemorySize,
                         SMEM_TOTAL);
    gemm_kernel<<<GRID_P, THREADS, SMEM_TOTAL>>>(out, alpha);
}